// round 8
// baseline (speedup 1.0000x reference)
#include <cuda_runtime.h>
#include <cuda_bf16.h>
#include <cstdint>

#define N_NODES 100000
#define N_EDGES 1600000
#define N_PAD   100096
#define NB_OFF  ((N_NODES + 511) / 512)   // 196

// ---------------- scratch (static device memory; no allocs) ----------------
__device__ float g_bufA[N_PAD * 128];   // h1 / h2 (pre-aggregation GEMM out)
__device__ float g_bufB[N_PAD * 128];   // out1
__device__ float g_bufC[N_PAD * 128];   // s = out2 + out1
__device__ int   g_deg[N_NODES];        // real in-edge count (no self-loop)
__device__ int   g_off[N_NODES];
__device__ int   g_cur[N_NODES];
__device__ int   g_csr_src[N_EDGES];
__device__ float g_csr_w[N_EDGES];
__device__ int   g_total[1];

// ---------------- f32x2 packed-FMA helpers (PTX-only on Blackwell) ---------
__device__ __forceinline__ unsigned long long pack2(float a, float b) {
    unsigned long long r;
    asm("mov.b64 %0, {%1, %2};" : "=l"(r) : "f"(a), "f"(b));
    return r;
}
__device__ __forceinline__ void unpack2(float& a, float& b, unsigned long long v) {
    asm("mov.b64 {%0, %1}, %2;" : "=f"(a), "=f"(b) : "l"(v));
}
__device__ __forceinline__ void fma2(unsigned long long& d, unsigned long long a,
                                     unsigned long long b, unsigned long long c) {
    asm("fma.rn.f32x2 %0, %1, %2, %3;" : "=l"(d) : "l"(a), "l"(b), "l"(c));
}

// ---------------- graph preprocessing (3 kernels) ----------------
__global__ void k_count(const int* __restrict__ ei) {
    int e = blockIdx.x * blockDim.x + threadIdx.x;
    if (e < N_EDGES) atomicAdd(&g_deg[ei[N_EDGES + e]], 1);
}

// one-pass offsets: block shuffle-scan + atomic block base (order-free CSR)
__global__ __launch_bounds__(512)
void k_offsets() {
    __shared__ int wsum[16];
    __shared__ int base;
    int tid  = threadIdx.x;
    int lane = tid & 31;
    int w    = tid >> 5;
    int i = blockIdx.x * 512 + tid;
    int v = (i < N_NODES) ? g_deg[i] : 0;

    int inc = v;
    #pragma unroll
    for (int o = 1; o < 32; o <<= 1) {
        int t = __shfl_up_sync(0xFFFFFFFFu, inc, o);
        if (lane >= o) inc += t;
    }
    if (lane == 31) wsum[w] = inc;
    __syncthreads();
    if (w == 0) {
        int s = (lane < 16) ? wsum[lane] : 0;
        #pragma unroll
        for (int o = 1; o < 16; o <<= 1) {
            int t = __shfl_up_sync(0xFFFFFFFFu, s, o);
            if (lane >= o) s += t;
        }
        if (lane < 16) wsum[lane] = s;
    }
    __syncthreads();
    if (tid == 0) base = atomicAdd(&g_total[0], wsum[15]);
    int excl = inc - v + (w > 0 ? wsum[w - 1] : 0);
    __syncthreads();
    if (i < N_NODES) {
        int o = base + excl;
        g_off[i] = o;
        g_cur[i] = o;
    }
}

__global__ void k_scatter(const int* __restrict__ ei) {
    int e = blockIdx.x * blockDim.x + threadIdx.x;
    if (e < N_EDGES) {
        int s = ei[e];
        int d = ei[N_EDGES + e];
        int p = atomicAdd(&g_cur[d], 1);
        float ws = rsqrtf((float)(g_deg[s] + 1));
        float wd = rsqrtf((float)(g_deg[d] + 1));
        g_csr_src[p] = s;
        g_csr_w[p]   = ws * wd;
    }
}

// ---------------- GEMM: C[N,128] = A[N,128] @ W[128,128] (f32x2 packed) ----
// Two-phase k-split (64 k per phase): smem 64KB -> 2 CTAs/SM for latency hiding.
__global__ __launch_bounds__(256, 2)
void k_gemm128(const float* __restrict__ A, const float* __restrict__ W,
               float* __restrict__ C) {
    extern __shared__ float sm[];
    float* As = sm;             // [k(64)][m(128)]  transposed A half-tile
    float* Ws = sm + 64 * 128;  // [k(64)][n(128)]
    int tid  = threadIdx.x;
    int row0 = blockIdx.x * 128;
    int tx = tid & 15, ty = tid >> 4;    // 8x8 micro-tile per thread

    unsigned long long acc[8][4];
    #pragma unroll
    for (int i = 0; i < 8; i++)
        #pragma unroll
        for (int j = 0; j < 4; j++) acc[i][j] = 0ull;

    const float4* Ag = (const float4*)A;

    #pragma unroll
    for (int ph = 0; ph < 2; ph++) {
        int kb = ph * 64;
        // load W half: Ws[k][n], 2048 float4, 8 per thread
        {
            const float4* Wg  = (const float4*)(W + kb * 128);
            float4*       Wsh = (float4*)Ws;
            #pragma unroll
            for (int i = 0; i < 8; i++) Wsh[tid + 256 * i] = Wg[tid + 256 * i];
        }
        // load A half transposed: thread r = tid>>1, k-quarter (tid&1)*32
        {
            int r  = tid >> 1;
            int kh = (tid & 1) * 32;
            int gr = row0 + r;
            #pragma unroll
            for (int j = 0; j < 8; j++) {
                int k = kh + j * 4;                     // 0..63 within half
                float4 v = make_float4(0.f, 0.f, 0.f, 0.f);
                if (gr < N_NODES) v = Ag[gr * 32 + ((kb + k) >> 2)];
                As[(k + 0) * 128 + r] = v.x;
                As[(k + 1) * 128 + r] = v.y;
                As[(k + 2) * 128 + r] = v.z;
                As[(k + 3) * 128 + r] = v.w;
            }
        }
        __syncthreads();

        #pragma unroll 8
        for (int k = 0; k < 64; k++) {
            float4 a0 = *(const float4*)&As[k * 128 + ty * 8];
            float4 a1 = *(const float4*)&As[k * 128 + ty * 8 + 4];
            const unsigned long long* Bp =
                (const unsigned long long*)&Ws[k * 128 + tx * 8];
            unsigned long long bb0 = Bp[0], bb1 = Bp[1], bb2 = Bp[2], bb3 = Bp[3];
            float av[8] = {a0.x, a0.y, a0.z, a0.w, a1.x, a1.y, a1.z, a1.w};
            #pragma unroll
            for (int i = 0; i < 8; i++) {
                unsigned long long aa = pack2(av[i], av[i]);
                fma2(acc[i][0], aa, bb0, acc[i][0]);
                fma2(acc[i][1], aa, bb1, acc[i][1]);
                fma2(acc[i][2], aa, bb2, acc[i][2]);
                fma2(acc[i][3], aa, bb3, acc[i][3]);
            }
        }
        __syncthreads();
    }

    float4* Cg = (float4*)C;
    #pragma unroll
    for (int i = 0; i < 8; i++) {
        int row = row0 + ty * 8 + i;
        if (row < N_NODES) {
            float4 lo, hi;
            unpack2(lo.x, lo.y, acc[i][0]);
            unpack2(lo.z, lo.w, acc[i][1]);
            unpack2(hi.x, hi.y, acc[i][2]);
            unpack2(hi.z, hi.w, acc[i][3]);
            Cg[row * 32 + tx * 2]     = lo;
            Cg[row * 32 + tx * 2 + 1] = hi;
        }
    }
}

// ---------------- aggregation: one warp per node, float4 per lane ----------
__global__ __launch_bounds__(256)
void k_agg(const float* __restrict__ h, const float* __restrict__ bias,
           const float* __restrict__ prev, float* __restrict__ out,
           int addprev) {
    int warp = threadIdx.x >> 5;
    int lane = threadIdx.x & 31;
    int i = blockIdx.x * 8 + warp;
    if (i >= N_NODES) return;

    const float4* h4 = (const float4*)h;
    int   cnt = g_deg[i];
    float di  = rsqrtf((float)(cnt + 1));
    float sl  = di * di;                      // self-loop weight
    float4 acc = h4[i * 32 + lane];
    acc.x *= sl; acc.y *= sl; acc.z *= sl; acc.w *= sl;

    int base = g_off[i];
    int e = 0;
    for (; e + 8 <= cnt; e += 8) {
        int s[8]; float w[8];
        #pragma unroll
        for (int j = 0; j < 8; j++) {
            s[j] = g_csr_src[base + e + j];
            w[j] = g_csr_w[base + e + j];
        }
        float4 v[8];
        #pragma unroll
        for (int j = 0; j < 8; j++) v[j] = h4[s[j] * 32 + lane];
        #pragma unroll
        for (int j = 0; j < 8; j++) {
            acc.x += w[j] * v[j].x; acc.y += w[j] * v[j].y;
            acc.z += w[j] * v[j].z; acc.w += w[j] * v[j].w;
        }
    }
    for (; e < cnt; e++) {
        int   sj = g_csr_src[base + e];
        float wj = g_csr_w[base + e];
        float4 v = h4[sj * 32 + lane];
        acc.x += wj * v.x; acc.y += wj * v.y;
        acc.z += wj * v.z; acc.w += wj * v.w;
    }

    float4 bv = ((const float4*)bias)[lane];
    acc.x = fmaxf(acc.x + bv.x, 0.f);
    acc.y = fmaxf(acc.y + bv.y, 0.f);
    acc.z = fmaxf(acc.z + bv.z, 0.f);
    acc.w = fmaxf(acc.w + bv.w, 0.f);

    if (addprev) {
        float4 p = ((const float4*)prev)[i * 32 + lane];
        acc.x += p.x; acc.y += p.y; acc.z += p.z; acc.w += p.w;
    }
    ((float4*)out)[i * 32 + lane] = acc;
}

// ---------------- classifier GEMM: C[N,40] = S[N,128] @ Wc[128,40] + bc ----
__global__ __launch_bounds__(256, 1)
void k_gemm40(const float* __restrict__ A, const float* __restrict__ W,
              const float* __restrict__ bias, float* __restrict__ C) {
    extern __shared__ float smf[];
    float* As = smf;               // [k][m] 128x128
    float* Ws = smf + 128 * 128;   // [k][40]
    int tid  = threadIdx.x;
    int row0 = blockIdx.x * 128;

    for (int idx = tid; idx < 128 * 40; idx += 256) Ws[idx] = W[idx];
    {
        int r  = tid >> 1;
        int kh = (tid & 1) * 64;
        int gr = row0 + r;
        const float4* Ag = (const float4*)A;
        #pragma unroll
        for (int j = 0; j < 16; j++) {
            int k = kh + j * 4;
            float4 v = make_float4(0.f, 0.f, 0.f, 0.f);
            if (gr < N_NODES) v = Ag[gr * 32 + (k >> 2)];
            As[(k + 0) * 128 + r] = v.x;
            As[(k + 1) * 128 + r] = v.y;
            As[(k + 2) * 128 + r] = v.z;
            As[(k + 3) * 128 + r] = v.w;
        }
    }
    __syncthreads();

    int rg = tid >> 3;          // 32 row groups of 4 rows
    int c0 = (tid & 7) * 5;     // 8 col groups of 5 cols
    unsigned long long acc2[2][5];   // row-pairs (0,1),(2,3) x 5 cols
    #pragma unroll
    for (int i = 0; i < 2; i++)
        #pragma unroll
        for (int j = 0; j < 5; j++) acc2[i][j] = 0ull;

    #pragma unroll 4
    for (int k = 0; k < 128; k++) {
        float4 a = *(const float4*)&As[k * 128 + rg * 4];
        unsigned long long a01 = pack2(a.x, a.y);
        unsigned long long a23 = pack2(a.z, a.w);
        #pragma unroll
        for (int j = 0; j < 5; j++) {
            float b = Ws[k * 40 + c0 + j];
            unsigned long long bb = pack2(b, b);
            fma2(acc2[0][j], a01, bb, acc2[0][j]);
            fma2(acc2[1][j], a23, bb, acc2[1][j]);
        }
    }

    float bcv[5];
    #pragma unroll
    for (int j = 0; j < 5; j++) bcv[j] = bias[c0 + j];
    #pragma unroll
    for (int i = 0; i < 2; i++) {
        float r0[5], r1[5];
        #pragma unroll
        for (int j = 0; j < 5; j++) unpack2(r0[j], r1[j], acc2[i][j]);
        int rowa = row0 + rg * 4 + 2 * i;
        int rowb = rowa + 1;
        if (rowa < N_NODES) {
            #pragma unroll
            for (int j = 0; j < 5; j++) C[rowa * 40 + c0 + j] = r0[j] + bcv[j];
        }
        if (rowb < N_NODES) {
            #pragma unroll
            for (int j = 0; j < 5; j++) C[rowb * 40 + c0 + j] = r1[j] + bcv[j];
        }
    }
}

// ---------------- launch ----------------
extern "C" void kernel_launch(void* const* d_in, const int* in_sizes, int n_in,
                              void* d_out, int out_size) {
    const float* x  = (const float*)d_in[0];
    const float* W1 = (const float*)d_in[1];
    const float* b1 = (const float*)d_in[2];
    const float* W2 = (const float*)d_in[3];
    const float* b2 = (const float*)d_in[4];
    const float* Wc = (const float*)d_in[5];
    const float* bc = (const float*)d_in[6];
    const int*   ei = (const int*)d_in[7];
    float* out = (float*)d_out;

    const int SMEM_G128 = 2 * 64 * 128 * 4;                   // 64 KB
    const int SMEM_G40  = 128 * 128 * 4 + 128 * 40 * 4;       // 84.5 KB
    cudaFuncSetAttribute(k_gemm128, cudaFuncAttributeMaxDynamicSharedMemorySize, SMEM_G128);
    cudaFuncSetAttribute(k_gemm40,  cudaFuncAttributeMaxDynamicSharedMemorySize, SMEM_G40);

    float *pA, *pB, *pC;
    cudaGetSymbolAddress((void**)&pA, g_bufA);
    cudaGetSymbolAddress((void**)&pB, g_bufB);
    cudaGetSymbolAddress((void**)&pC, g_bufC);
    int *pDeg, *pTot;
    cudaGetSymbolAddress((void**)&pDeg, g_deg);
    cudaGetSymbolAddress((void**)&pTot, g_total);

    const int GE  = (N_EDGES + 255) / 256;   // 6250
    const int GT  = (N_NODES + 127) / 128;   // 782
    const int GAG = (N_NODES + 7) / 8;       // 12500

    // zero degree counters + offset ticket (graph-capturable async memsets)
    cudaMemsetAsync(pDeg, 0, N_NODES * sizeof(int));
    cudaMemsetAsync(pTot, 0, sizeof(int));

    // preprocessing: 3 kernels
    k_count<<<GE, 256>>>(ei);
    k_offsets<<<NB_OFF, 512>>>();
    k_scatter<<<GE, 256>>>(ei);

    // layer 1
    k_gemm128<<<GT, 256, SMEM_G128>>>(x, W1, pA);
    k_agg<<<GAG, 256>>>(pA, b1, nullptr, pB, 0);
    // layer 2
    k_gemm128<<<GT, 256, SMEM_G128>>>(pB, W2, pA);
    k_agg<<<GAG, 256>>>(pA, b2, pB, pC, 1);
    // classifier
    k_gemm40<<<GT, 256, SMEM_G40>>>(pC, Wc, bc, out);
}

// round 9
// speedup vs baseline: 1.0364x; 1.0364x over previous
#include <cuda_runtime.h>
#include <cuda_bf16.h>
#include <cstdint>

#define N_NODES 100000
#define N_EDGES 1600000
#define N_PAD   100096
#define NB_OFF  ((N_NODES + 511) / 512)   // 196

// ---------------- scratch (static device memory; no allocs) ----------------
__device__ float g_bufA[N_PAD * 128];   // h1 / h2 (pre-aggregation GEMM out)
__device__ float g_bufB[N_PAD * 128];   // out1
__device__ float g_bufC[N_PAD * 128];   // s = out2 + out1
__device__ int   g_deg[N_NODES];        // real in-edge count (no self-loop)
__device__ int   g_off[N_NODES];
__device__ int   g_cur[N_NODES];
__device__ int2  g_csr[N_EDGES];        // .x = src, .y = weight bits
__device__ int   g_total[1];

// ---------------- f32x2 packed-FMA helpers (PTX-only on Blackwell) ---------
__device__ __forceinline__ unsigned long long pack2(float a, float b) {
    unsigned long long r;
    asm("mov.b64 %0, {%1, %2};" : "=l"(r) : "f"(a), "f"(b));
    return r;
}
__device__ __forceinline__ void unpack2(float& a, float& b, unsigned long long v) {
    asm("mov.b64 {%0, %1}, %2;" : "=f"(a), "=f"(b) : "l"(v));
}
__device__ __forceinline__ void fma2(unsigned long long& d, unsigned long long a,
                                     unsigned long long b, unsigned long long c) {
    asm("fma.rn.f32x2 %0, %1, %2, %3;" : "=l"(d) : "l"(a), "l"(b), "l"(c));
}

// ---------------- graph preprocessing ----------------
__global__ void k_zero() {
    int i = blockIdx.x * blockDim.x + threadIdx.x;
    if (i < N_NODES) g_deg[i] = 0;
    if (i == 0) g_total[0] = 0;
}

__global__ void k_count(const int* __restrict__ ei) {
    int e = blockIdx.x * blockDim.x + threadIdx.x;
    if (e < N_EDGES) atomicAdd(&g_deg[ei[N_EDGES + e]], 1);
}

// one-pass offsets: block shuffle-scan + atomic block base (order-free CSR)
__global__ __launch_bounds__(512)
void k_offsets() {
    __shared__ int wsum[16];
    __shared__ int base;
    int tid  = threadIdx.x;
    int lane = tid & 31;
    int w    = tid >> 5;
    int i = blockIdx.x * 512 + tid;
    int v = (i < N_NODES) ? g_deg[i] : 0;

    int inc = v;
    #pragma unroll
    for (int o = 1; o < 32; o <<= 1) {
        int t = __shfl_up_sync(0xFFFFFFFFu, inc, o);
        if (lane >= o) inc += t;
    }
    if (lane == 31) wsum[w] = inc;
    __syncthreads();
    if (w == 0) {
        int s = (lane < 16) ? wsum[lane] : 0;
        #pragma unroll
        for (int o = 1; o < 16; o <<= 1) {
            int t = __shfl_up_sync(0xFFFFFFFFu, s, o);
            if (lane >= o) s += t;
        }
        if (lane < 16) wsum[lane] = s;
    }
    __syncthreads();
    if (tid == 0) base = atomicAdd(&g_total[0], wsum[15]);
    int excl = inc - v + (w > 0 ? wsum[w - 1] : 0);
    __syncthreads();
    if (i < N_NODES) {
        int o = base + excl;
        g_off[i] = o;
        g_cur[i] = o;
    }
}

__global__ void k_scatter(const int* __restrict__ ei) {
    int e = blockIdx.x * blockDim.x + threadIdx.x;
    if (e < N_EDGES) {
        int s = ei[e];
        int d = ei[N_EDGES + e];
        int p = atomicAdd(&g_cur[d], 1);
        float ws = rsqrtf((float)(g_deg[s] + 1));
        float wd = rsqrtf((float)(g_deg[d] + 1));
        int2 v;
        v.x = s;
        v.y = __float_as_int(ws * wd);
        g_csr[p] = v;
    }
}

// ---------------- GEMM: C[N,128] = A[N,128] @ W[128,128] (f32x2 packed) ----
// Full-tile version (R6-best, 93.4us); Ws inner loads as 2x LDS.128.
__global__ __launch_bounds__(256, 1)
void k_gemm128(const float* __restrict__ A, const float* __restrict__ W,
               float* __restrict__ C) {
    extern __shared__ float sm[];
    float* As = sm;              // [k][m]  (transposed A tile), 128x128
    float* Ws = sm + 128 * 128;  // [k][n], 128x128
    int tid  = threadIdx.x;
    int row0 = blockIdx.x * 128;

    {
        const float4* Wg  = (const float4*)W;
        float4*       Wsh = (float4*)Ws;
        #pragma unroll
        for (int i = 0; i < 16; i++) Wsh[tid + 256 * i] = Wg[tid + 256 * i];
    }
    {
        int r  = tid >> 1;
        int kh = (tid & 1) * 64;
        int gr = row0 + r;
        const float4* Ag = (const float4*)A;
        #pragma unroll
        for (int j = 0; j < 16; j++) {
            int k = kh + j * 4;
            float4 v = make_float4(0.f, 0.f, 0.f, 0.f);
            if (gr < N_NODES) v = Ag[gr * 32 + (k >> 2)];
            As[(k + 0) * 128 + r] = v.x;
            As[(k + 1) * 128 + r] = v.y;
            As[(k + 2) * 128 + r] = v.z;
            As[(k + 3) * 128 + r] = v.w;
        }
    }
    __syncthreads();

    int tx = tid & 15, ty = tid >> 4;    // 8x8 micro-tile per thread
    unsigned long long acc[8][4];
    #pragma unroll
    for (int i = 0; i < 8; i++)
        #pragma unroll
        for (int j = 0; j < 4; j++) acc[i][j] = 0ull;

    #pragma unroll 8
    for (int k = 0; k < 128; k++) {
        float4 a0 = *(const float4*)&As[k * 128 + ty * 8];
        float4 a1 = *(const float4*)&As[k * 128 + ty * 8 + 4];
        ulonglong2 q0 = *(const ulonglong2*)&Ws[k * 128 + tx * 8];
        ulonglong2 q1 = *(const ulonglong2*)&Ws[k * 128 + tx * 8 + 4];
        unsigned long long bb0 = q0.x, bb1 = q0.y, bb2 = q1.x, bb3 = q1.y;
        float av[8] = {a0.x, a0.y, a0.z, a0.w, a1.x, a1.y, a1.z, a1.w};
        #pragma unroll
        for (int i = 0; i < 8; i++) {
            unsigned long long aa = pack2(av[i], av[i]);
            fma2(acc[i][0], aa, bb0, acc[i][0]);
            fma2(acc[i][1], aa, bb1, acc[i][1]);
            fma2(acc[i][2], aa, bb2, acc[i][2]);
            fma2(acc[i][3], aa, bb3, acc[i][3]);
        }
    }

    float4* Cg = (float4*)C;
    #pragma unroll
    for (int i = 0; i < 8; i++) {
        int row = row0 + ty * 8 + i;
        if (row < N_NODES) {
            float4 lo, hi;
            unpack2(lo.x, lo.y, acc[i][0]);
            unpack2(lo.z, lo.w, acc[i][1]);
            unpack2(hi.x, hi.y, acc[i][2]);
            unpack2(hi.z, hi.w, acc[i][3]);
            Cg[row * 32 + tx * 2]     = lo;
            Cg[row * 32 + tx * 2 + 1] = hi;
        }
    }
}

// ---------------- aggregation: one warp per node, float4 per lane ----------
__global__ __launch_bounds__(256)
void k_agg(const float* __restrict__ h, const float* __restrict__ bias,
           const float* __restrict__ prev, float* __restrict__ out,
           int addprev) {
    int warp = threadIdx.x >> 5;
    int lane = threadIdx.x & 31;
    int i = blockIdx.x * 8 + warp;
    if (i >= N_NODES) return;

    const float4* h4 = (const float4*)h;
    int   cnt = g_deg[i];
    float di  = rsqrtf((float)(cnt + 1));
    float sl  = di * di;                      // self-loop weight
    float4 acc = h4[i * 32 + lane];
    acc.x *= sl; acc.y *= sl; acc.z *= sl; acc.w *= sl;

    int base = g_off[i];
    int e = 0;
    for (; e + 8 <= cnt; e += 8) {
        int s[8]; float w[8];
        #pragma unroll
        for (int j = 0; j < 8; j++) {
            int2 c = g_csr[base + e + j];
            s[j] = c.x;
            w[j] = __int_as_float(c.y);
        }
        float4 v[8];
        #pragma unroll
        for (int j = 0; j < 8; j++) v[j] = h4[s[j] * 32 + lane];
        #pragma unroll
        for (int j = 0; j < 8; j++) {
            acc.x += w[j] * v[j].x; acc.y += w[j] * v[j].y;
            acc.z += w[j] * v[j].z; acc.w += w[j] * v[j].w;
        }
    }
    for (; e < cnt; e++) {
        int2 c = g_csr[base + e];
        float wj = __int_as_float(c.y);
        float4 v = h4[c.x * 32 + lane];
        acc.x += wj * v.x; acc.y += wj * v.y;
        acc.z += wj * v.z; acc.w += wj * v.w;
    }

    float4 bv = ((const float4*)bias)[lane];
    acc.x = fmaxf(acc.x + bv.x, 0.f);
    acc.y = fmaxf(acc.y + bv.y, 0.f);
    acc.z = fmaxf(acc.z + bv.z, 0.f);
    acc.w = fmaxf(acc.w + bv.w, 0.f);

    if (addprev) {
        float4 p = ((const float4*)prev)[i * 32 + lane];
        acc.x += p.x; acc.y += p.y; acc.z += p.z; acc.w += p.w;
    }
    ((float4*)out)[i * 32 + lane] = acc;
}

// ---------------- classifier GEMM: C[N,40] = S[N,128] @ Wc[128,40] + bc ----
__global__ __launch_bounds__(256, 1)
void k_gemm40(const float* __restrict__ A, const float* __restrict__ W,
              const float* __restrict__ bias, float* __restrict__ C) {
    extern __shared__ float smf[];
    float* As = smf;               // [k][m] 128x128
    float* Ws = smf + 128 * 128;   // [k][40]
    int tid  = threadIdx.x;
    int row0 = blockIdx.x * 128;

    for (int idx = tid; idx < 128 * 40; idx += 256) Ws[idx] = W[idx];
    {
        int r  = tid >> 1;
        int kh = (tid & 1) * 64;
        int gr = row0 + r;
        const float4* Ag = (const float4*)A;
        #pragma unroll
        for (int j = 0; j < 16; j++) {
            int k = kh + j * 4;
            float4 v = make_float4(0.f, 0.f, 0.f, 0.f);
            if (gr < N_NODES) v = Ag[gr * 32 + (k >> 2)];
            As[(k + 0) * 128 + r] = v.x;
            As[(k + 1) * 128 + r] = v.y;
            As[(k + 2) * 128 + r] = v.z;
            As[(k + 3) * 128 + r] = v.w;
        }
    }
    __syncthreads();

    int rg = tid >> 3;          // 32 row groups of 4 rows
    int c0 = (tid & 7) * 5;     // 8 col groups of 5 cols
    unsigned long long acc2[2][5];   // row-pairs (0,1),(2,3) x 5 cols
    #pragma unroll
    for (int i = 0; i < 2; i++)
        #pragma unroll
        for (int j = 0; j < 5; j++) acc2[i][j] = 0ull;

    #pragma unroll 4
    for (int k = 0; k < 128; k++) {
        float4 a = *(const float4*)&As[k * 128 + rg * 4];
        unsigned long long a01 = pack2(a.x, a.y);
        unsigned long long a23 = pack2(a.z, a.w);
        #pragma unroll
        for (int j = 0; j < 5; j++) {
            float b = Ws[k * 40 + c0 + j];
            unsigned long long bb = pack2(b, b);
            fma2(acc2[0][j], a01, bb, acc2[0][j]);
            fma2(acc2[1][j], a23, bb, acc2[1][j]);
        }
    }

    float bcv[5];
    #pragma unroll
    for (int j = 0; j < 5; j++) bcv[j] = bias[c0 + j];
    #pragma unroll
    for (int i = 0; i < 2; i++) {
        float r0[5], r1[5];
        #pragma unroll
        for (int j = 0; j < 5; j++) unpack2(r0[j], r1[j], acc2[i][j]);
        int rowa = row0 + rg * 4 + 2 * i;
        int rowb = rowa + 1;
        if (rowa < N_NODES) {
            #pragma unroll
            for (int j = 0; j < 5; j++) C[rowa * 40 + c0 + j] = r0[j] + bcv[j];
        }
        if (rowb < N_NODES) {
            #pragma unroll
            for (int j = 0; j < 5; j++) C[rowb * 40 + c0 + j] = r1[j] + bcv[j];
        }
    }
}

// ---------------- launch ----------------
extern "C" void kernel_launch(void* const* d_in, const int* in_sizes, int n_in,
                              void* d_out, int out_size) {
    const float* x  = (const float*)d_in[0];
    const float* W1 = (const float*)d_in[1];
    const float* b1 = (const float*)d_in[2];
    const float* W2 = (const float*)d_in[3];
    const float* b2 = (const float*)d_in[4];
    const float* Wc = (const float*)d_in[5];
    const float* bc = (const float*)d_in[6];
    const int*   ei = (const int*)d_in[7];
    float* out = (float*)d_out;

    const int SMEM_G128 = 2 * 128 * 128 * 4;                  // 128 KB
    const int SMEM_G40  = 128 * 128 * 4 + 128 * 40 * 4;       // 84.5 KB
    cudaFuncSetAttribute(k_gemm128, cudaFuncAttributeMaxDynamicSharedMemorySize, SMEM_G128);
    cudaFuncSetAttribute(k_gemm40,  cudaFuncAttributeMaxDynamicSharedMemorySize, SMEM_G40);

    float *pA, *pB, *pC;
    cudaGetSymbolAddress((void**)&pA, g_bufA);
    cudaGetSymbolAddress((void**)&pB, g_bufB);
    cudaGetSymbolAddress((void**)&pC, g_bufC);

    const int GN  = (N_NODES + 255) / 256;   // 391
    const int GE  = (N_EDGES + 255) / 256;   // 6250
    const int GT  = (N_NODES + 127) / 128;   // 782
    const int GAG = (N_NODES + 7) / 8;       // 12500

    // preprocessing: 4 kernels (zero + count + offsets + scatter)
    k_zero<<<GN, 256>>>();
    k_count<<<GE, 256>>>(ei);
    k_offsets<<<NB_OFF, 512>>>();
    k_scatter<<<GE, 256>>>(ei);

    // layer 1
    k_gemm128<<<GT, 256, SMEM_G128>>>(x, W1, pA);
    k_agg<<<GAG, 256>>>(pA, b1, nullptr, pB, 0);       // 6th launch -> ncu window
    // layer 2
    k_gemm128<<<GT, 256, SMEM_G128>>>(pB, W2, pA);
    k_agg<<<GAG, 256>>>(pA, b2, pB, pC, 1);
    // classifier
    k_gemm40<<<GT, 256, SMEM_G40>>>(pC, Wc, bc, out);
}

// round 11
// speedup vs baseline: 1.5832x; 1.5275x over previous
#include <cuda_runtime.h>
#include <cuda_bf16.h>
#include <cstdint>

#define N_NODES 100000
#define N_EDGES 1600000
#define N_PAD   100096
#define NB_OFF  ((N_NODES + 511) / 512)   // 196

// ---------------- scratch (static device memory; no allocs) ----------------
__device__ float g_bufA[N_PAD * 128];   // p = dinv*h (scaled GEMM out)
__device__ float g_bufB[N_PAD * 128];   // out1
__device__ float g_bufC[N_PAD * 128];   // s = out2 + out1
__device__ int   g_deg[N_NODES];        // real in-edge count (no self-loop)
__device__ int   g_off[N_NODES];
__device__ int   g_cur[N_NODES];
__device__ int   g_csr_src[N_EDGES];
__device__ int   g_total[1];

// ---------------- f32x2 packed-FMA helpers (PTX-only on Blackwell) ---------
__device__ __forceinline__ unsigned long long pack2(float a, float b) {
    unsigned long long r;
    asm("mov.b64 %0, {%1, %2};" : "=l"(r) : "f"(a), "f"(b));
    return r;
}
__device__ __forceinline__ void unpack2(float& a, float& b, unsigned long long v) {
    asm("mov.b64 {%0, %1}, %2;" : "=f"(a), "=f"(b) : "l"(v));
}
__device__ __forceinline__ void fma2(unsigned long long& d, unsigned long long a,
                                     unsigned long long b, unsigned long long c) {
    asm("fma.rn.f32x2 %0, %1, %2, %3;" : "=l"(d) : "l"(a), "l"(b), "l"(c));
}

// ---------------- graph preprocessing (3 kernels + memsets) ----------------
__global__ void k_count(const int* __restrict__ ei) {
    int e = blockIdx.x * blockDim.x + threadIdx.x;
    if (e < N_EDGES) atomicAdd(&g_deg[ei[N_EDGES + e]], 1);
}

// one-pass offsets: block shuffle-scan + atomic block base (order-free CSR)
__global__ __launch_bounds__(512)
void k_offsets() {
    __shared__ int wsum[16];
    __shared__ int base;
    int tid  = threadIdx.x;
    int lane = tid & 31;
    int w    = tid >> 5;
    int i = blockIdx.x * 512 + tid;
    int v = (i < N_NODES) ? g_deg[i] : 0;

    int inc = v;
    #pragma unroll
    for (int o = 1; o < 32; o <<= 1) {
        int t = __shfl_up_sync(0xFFFFFFFFu, inc, o);
        if (lane >= o) inc += t;
    }
    if (lane == 31) wsum[w] = inc;
    __syncthreads();
    if (w == 0) {
        int s = (lane < 16) ? wsum[lane] : 0;
        #pragma unroll
        for (int o = 1; o < 16; o <<= 1) {
            int t = __shfl_up_sync(0xFFFFFFFFu, s, o);
            if (lane >= o) s += t;
        }
        if (lane < 16) wsum[lane] = s;
    }
    __syncthreads();
    if (tid == 0) base = atomicAdd(&g_total[0], wsum[15]);
    int excl = inc - v + (w > 0 ? wsum[w - 1] : 0);
    __syncthreads();
    if (i < N_NODES) {
        int o = base + excl;
        g_off[i] = o;
        g_cur[i] = o;
    }
}

// weights are folded into the GEMM epilogue: scatter stores src index only
__global__ void k_scatter(const int* __restrict__ ei) {
    int e = blockIdx.x * blockDim.x + threadIdx.x;
    if (e < N_EDGES) {
        int s = ei[e];
        int d = ei[N_EDGES + e];
        int p = atomicAdd(&g_cur[d], 1);
        g_csr_src[p] = s;
    }
}

// ---------------- GEMM: C[N,128] = dinv * (A[N,128] @ W[128,128]) ---------
// Exact R6-best body; epilogue scales each output row by rsqrt(deg+1).
__global__ __launch_bounds__(256, 1)
void k_gemm128(const float* __restrict__ A, const float* __restrict__ W,
               float* __restrict__ C) {
    extern __shared__ float sm[];
    float* As = sm;              // [k][m]  (transposed A tile), 128x128
    float* Ws = sm + 128 * 128;  // [k][n], 128x128
    int tid  = threadIdx.x;
    int row0 = blockIdx.x * 128;

    {
        const float4* Wg  = (const float4*)W;
        float4*       Wsh = (float4*)Ws;
        #pragma unroll
        for (int i = 0; i < 16; i++) Wsh[tid + 256 * i] = Wg[tid + 256 * i];
    }
    {
        int r  = tid >> 1;
        int kh = (tid & 1) * 64;
        int gr = row0 + r;
        const float4* Ag = (const float4*)A;
        #pragma unroll
        for (int j = 0; j < 16; j++) {
            int k = kh + j * 4;
            float4 v = make_float4(0.f, 0.f, 0.f, 0.f);
            if (gr < N_NODES) v = Ag[gr * 32 + (k >> 2)];
            As[(k + 0) * 128 + r] = v.x;
            As[(k + 1) * 128 + r] = v.y;
            As[(k + 2) * 128 + r] = v.z;
            As[(k + 3) * 128 + r] = v.w;
        }
    }
    __syncthreads();

    int tx = tid & 15, ty = tid >> 4;    // 8x8 micro-tile per thread
    unsigned long long acc[8][4];
    #pragma unroll
    for (int i = 0; i < 8; i++)
        #pragma unroll
        for (int j = 0; j < 4; j++) acc[i][j] = 0ull;

    #pragma unroll 8
    for (int k = 0; k < 128; k++) {
        float4 a0 = *(const float4*)&As[k * 128 + ty * 8];
        float4 a1 = *(const float4*)&As[k * 128 + ty * 8 + 4];
        const unsigned long long* Bp =
            (const unsigned long long*)&Ws[k * 128 + tx * 8];
        unsigned long long bb0 = Bp[0], bb1 = Bp[1], bb2 = Bp[2], bb3 = Bp[3];
        float av[8] = {a0.x, a0.y, a0.z, a0.w, a1.x, a1.y, a1.z, a1.w};
        #pragma unroll
        for (int i = 0; i < 8; i++) {
            unsigned long long aa = pack2(av[i], av[i]);
            fma2(acc[i][0], aa, bb0, acc[i][0]);
            fma2(acc[i][1], aa, bb1, acc[i][1]);
            fma2(acc[i][2], aa, bb2, acc[i][2]);
            fma2(acc[i][3], aa, bb3, acc[i][3]);
        }
    }

    float4* Cg = (float4*)C;
    #pragma unroll
    for (int i = 0; i < 8; i++) {
        int row = row0 + ty * 8 + i;
        if (row < N_NODES) {
            float di = rsqrtf((float)(g_deg[row] + 1));
            float4 lo, hi;
            unpack2(lo.x, lo.y, acc[i][0]);
            unpack2(lo.z, lo.w, acc[i][1]);
            unpack2(hi.x, hi.y, acc[i][2]);
            unpack2(hi.z, hi.w, acc[i][3]);
            lo.x *= di; lo.y *= di; lo.z *= di; lo.w *= di;
            hi.x *= di; hi.y *= di; hi.z *= di; hi.w *= di;
            Cg[row * 32 + tx * 2]     = lo;
            Cg[row * 32 + tx * 2 + 1] = hi;
        }
    }
}

// ---------------- aggregation: one warp per node, float4 per lane ----------
// p = dinv*h is pre-scaled; out[d] = relu( dinv[d] * (p[d] + sum p[s]) + b )
__global__ __launch_bounds__(256)
void k_agg(const float* __restrict__ p_in, const float* __restrict__ bias,
           const float* __restrict__ prev, float* __restrict__ out,
           int addprev) {
    int warp = threadIdx.x >> 5;
    int lane = threadIdx.x & 31;
    int i = blockIdx.x * 8 + warp;
    if (i >= N_NODES) return;

    const float4* h4 = (const float4*)p_in;
    int   cnt = g_deg[i];
    float di  = rsqrtf((float)(cnt + 1));
    float4 acc = h4[i * 32 + lane];            // p[d] (covers the self loop)

    int base = g_off[i];
    int e = 0;
    for (; e + 8 <= cnt; e += 8) {
        int s[8];
        #pragma unroll
        for (int j = 0; j < 8; j++) s[j] = g_csr_src[base + e + j];
        float4 v[8];
        #pragma unroll
        for (int j = 0; j < 8; j++) v[j] = h4[s[j] * 32 + lane];
        #pragma unroll
        for (int j = 0; j < 8; j++) {
            acc.x += v[j].x; acc.y += v[j].y;
            acc.z += v[j].z; acc.w += v[j].w;
        }
    }
    for (; e < cnt; e++) {
        float4 v = h4[g_csr_src[base + e] * 32 + lane];
        acc.x += v.x; acc.y += v.y; acc.z += v.z; acc.w += v.w;
    }

    float4 bv = ((const float4*)bias)[lane];
    acc.x = fmaxf(fmaf(acc.x, di, bv.x), 0.f);
    acc.y = fmaxf(fmaf(acc.y, di, bv.y), 0.f);
    acc.z = fmaxf(fmaf(acc.z, di, bv.z), 0.f);
    acc.w = fmaxf(fmaf(acc.w, di, bv.w), 0.f);

    if (addprev) {
        float4 p = ((const float4*)prev)[i * 32 + lane];
        acc.x += p.x; acc.y += p.y; acc.z += p.z; acc.w += p.w;
    }
    ((float4*)out)[i * 32 + lane] = acc;
}

// ---------------- classifier GEMM: C[N,40] = S[N,128] @ Wc[128,40] + bc ----
__global__ __launch_bounds__(256, 1)
void k_gemm40(const float* __restrict__ A, const float* __restrict__ W,
              const float* __restrict__ bias, float* __restrict__ C) {
    extern __shared__ float smf[];
    float* As = smf;               // [k][m] 128x128
    float* Ws = smf + 128 * 128;   // [k][40]
    int tid  = threadIdx.x;
    int row0 = blockIdx.x * 128;

    for (int idx = tid; idx < 128 * 40; idx += 256) Ws[idx] = W[idx];
    {
        int r  = tid >> 1;
        int kh = (tid & 1) * 64;
        int gr = row0 + r;
        const float4* Ag = (const float4*)A;
        #pragma unroll
        for (int j = 0; j < 16; j++) {
            int k = kh + j * 4;
            float4 v = make_float4(0.f, 0.f, 0.f, 0.f);
            if (gr < N_NODES) v = Ag[gr * 32 + (k >> 2)];
            As[(k + 0) * 128 + r] = v.x;
            As[(k + 1) * 128 + r] = v.y;
            As[(k + 2) * 128 + r] = v.z;
            As[(k + 3) * 128 + r] = v.w;
        }
    }
    __syncthreads();

    int rg = tid >> 3;          // 32 row groups of 4 rows
    int c0 = (tid & 7) * 5;     // 8 col groups of 5 cols
    unsigned long long acc2[2][5];   // row-pairs (0,1),(2,3) x 5 cols
    #pragma unroll
    for (int i = 0; i < 2; i++)
        #pragma unroll
        for (int j = 0; j < 5; j++) acc2[i][j] = 0ull;

    #pragma unroll 4
    for (int k = 0; k < 128; k++) {
        float4 a = *(const float4*)&As[k * 128 + rg * 4];
        unsigned long long a01 = pack2(a.x, a.y);
        unsigned long long a23 = pack2(a.z, a.w);
        #pragma unroll
        for (int j = 0; j < 5; j++) {
            float b = Ws[k * 40 + c0 + j];
            unsigned long long bb = pack2(b, b);
            fma2(acc2[0][j], a01, bb, acc2[0][j]);
            fma2(acc2[1][j], a23, bb, acc2[1][j]);
        }
    }

    float bcv[5];
    #pragma unroll
    for (int j = 0; j < 5; j++) bcv[j] = bias[c0 + j];
    #pragma unroll
    for (int i = 0; i < 2; i++) {
        float r0[5], r1[5];
        #pragma unroll
        for (int j = 0; j < 5; j++) unpack2(r0[j], r1[j], acc2[i][j]);
        int rowa = row0 + rg * 4 + 2 * i;
        int rowb = rowa + 1;
        if (rowa < N_NODES) {
            #pragma unroll
            for (int j = 0; j < 5; j++) C[rowa * 40 + c0 + j] = r0[j] + bcv[j];
        }
        if (rowb < N_NODES) {
            #pragma unroll
            for (int j = 0; j < 5; j++) C[rowb * 40 + c0 + j] = r1[j] + bcv[j];
        }
    }
}

// ---------------- launch ----------------
extern "C" void kernel_launch(void* const* d_in, const int* in_sizes, int n_in,
                              void* d_out, int out_size) {
    const float* x  = (const float*)d_in[0];
    const float* W1 = (const float*)d_in[1];
    const float* b1 = (const float*)d_in[2];
    const float* W2 = (const float*)d_in[3];
    const float* b2 = (const float*)d_in[4];
    const float* Wc = (const float*)d_in[5];
    const float* bc = (const float*)d_in[6];
    const int*   ei = (const int*)d_in[7];
    float* out = (float*)d_out;

    const int SMEM_G128 = 2 * 128 * 128 * 4;                  // 128 KB
    const int SMEM_G40  = 128 * 128 * 4 + 128 * 40 * 4;       // 84.5 KB
    cudaFuncSetAttribute(k_gemm128, cudaFuncAttributeMaxDynamicSharedMemorySize, SMEM_G128);
    cudaFuncSetAttribute(k_gemm40,  cudaFuncAttributeMaxDynamicSharedMemorySize, SMEM_G40);

    float *pA, *pB, *pC;
    cudaGetSymbolAddress((void**)&pA, g_bufA);
    cudaGetSymbolAddress((void**)&pB, g_bufB);
    cudaGetSymbolAddress((void**)&pC, g_bufC);
    int *pDeg, *pTot;
    cudaGetSymbolAddress((void**)&pDeg, g_deg);
    cudaGetSymbolAddress((void**)&pTot, g_total);

    const int GE  = (N_EDGES + 255) / 256;   // 6250
    const int GT  = (N_NODES + 127) / 128;   // 782
    const int GAG = N_PAD / 128 * 16;        // 12512 warps-worth: (N_PAD/8)/... -> blocks below

    // zero degree counters + offset ticket (graph-capturable async memsets)
    cudaMemsetAsync(pDeg, 0, N_NODES * sizeof(int));
    cudaMemsetAsync(pTot, 0, sizeof(int));

    // preprocessing
    k_count<<<GE, 256>>>(ei);
    k_offsets<<<NB_OFF, 512>>>();
    k_scatter<<<GE, 256>>>(ei);

    // layer 1 (k_gemm128 is the 4th kernel launch -> ncu window)
    k_gemm128<<<GT, 256, SMEM_G128>>>(x, W1, pA);
    k_agg<<<(N_NODES + 7) / 8, 256>>>(pA, b1, nullptr, pB, 0);
    // layer 2
    k_gemm128<<<GT, 256, SMEM_G128>>>(pB, W2, pA);
    k_agg<<<(N_NODES + 7) / 8, 256>>>(pA, b2, pB, pC, 1);
    // classifier
    k_gemm40<<<GT, 256, SMEM_G40>>>(pC, Wc, bc, out);
    (void)GAG;
}